// round 15
// baseline (speedup 1.0000x reference)
#include <cuda_runtime.h>
#include <cuda_bf16.h>
#include <math.h>

#define N_NODES 4096
#define N_EDGES 131072
#define IN_CH   128
#define H       256
#define NCLS    16
#define NHEAD   4
#define HD      64
#define KSPLIT  2
#define EPS     1e-5f

// ---------------- device scratch (static, no allocs) ----------------
__device__ float g_deg[N_NODES];
__device__ float g_dinv[N_NODES];
__device__ int   g_cnt[N_NODES];
__device__ int   g_rowptr[N_NODES + 1];
__device__ int   g_cursor[N_NODES];
__device__ int   g_eidx[N_EDGES];

__device__ __align__(16) float g_h   [N_NODES * H];       // gemm scratch
__device__ __align__(16) float g_g1  [N_NODES * H];       // gcn1 out (relu)
__device__ __align__(16) float g_xl  [N_NODES * H];       // x_local
__device__ __align__(16) __nv_bfloat16 g_qkvb[N_NODES * 3 * H];  // bf16 QKV (Q pre-scaled)
__device__ __align__(16) float g_x1  [N_NODES * H];       // after ln1
__device__ __align__(16) float g_ffn [N_NODES * 4 * H];
__device__ __align__(16) float g_f2  [N_NODES * H];
__device__ __align__(16) float g_xf  [N_NODES * H];       // x_final
__device__ __align__(16) float g_d1  [N_NODES * 2 * H];
__device__ __align__(16) float g_pacc[NHEAD * KSPLIT * N_NODES * HD];
__device__ float g_pm[NHEAD * KSPLIT * N_NODES];
__device__ float g_pl[NHEAD * KSPLIT * N_NODES];

// ---------------- asm helpers ----------------
__device__ __forceinline__ unsigned sptr(const void* p) {
    return (unsigned)__cvta_generic_to_shared(p);
}
__device__ __forceinline__ void cpa16(unsigned dst, const void* src) {
    asm volatile("cp.async.ca.shared.global [%0], [%1], 16;" :: "r"(dst), "l"(src));
}
__device__ __forceinline__ void cpa_commit() {
    asm volatile("cp.async.commit_group;");
}
__device__ __forceinline__ void cpa_wait1() {
    asm volatile("cp.async.wait_group 1;");
}
__device__ __forceinline__ void ldm4(unsigned& r0, unsigned& r1, unsigned& r2, unsigned& r3,
                                     unsigned addr) {
    asm volatile("ldmatrix.sync.aligned.m8n8.x4.shared.b16 {%0,%1,%2,%3},[%4];"
                 : "=r"(r0), "=r"(r1), "=r"(r2), "=r"(r3) : "r"(addr));
}
__device__ __forceinline__ void ldm4t(unsigned& r0, unsigned& r1, unsigned& r2, unsigned& r3,
                                      unsigned addr) {
    asm volatile("ldmatrix.sync.aligned.m8n8.x4.trans.shared.b16 {%0,%1,%2,%3},[%4];"
                 : "=r"(r0), "=r"(r1), "=r"(r2), "=r"(r3) : "r"(addr));
}
__device__ __forceinline__ void mma_bf16(float* d, const unsigned* a, const unsigned* b) {
    asm volatile("mma.sync.aligned.m16n8k16.row.col.f32.bf16.bf16.f32 "
                 "{%0,%1,%2,%3},{%4,%5,%6,%7},{%8,%9},{%0,%1,%2,%3};"
                 : "+f"(d[0]), "+f"(d[1]), "+f"(d[2]), "+f"(d[3])
                 : "r"(a[0]), "r"(a[1]), "r"(a[2]), "r"(a[3]), "r"(b[0]), "r"(b[1]));
}
__device__ __forceinline__ void mma_tf32(float* d, const unsigned* a, const unsigned* b) {
    asm volatile("mma.sync.aligned.m16n8k8.row.col.f32.tf32.tf32.f32 "
                 "{%0,%1,%2,%3},{%4,%5,%6,%7},{%8,%9},{%0,%1,%2,%3};"
                 : "+f"(d[0]), "+f"(d[1]), "+f"(d[2]), "+f"(d[3])
                 : "r"(a[0]), "r"(a[1]), "r"(a[2]), "r"(a[3]), "r"(b[0]), "r"(b[1]));
}
__device__ __forceinline__ unsigned packbf(float lo, float hi) {
    unsigned r;
    asm("cvt.rn.bf16x2.f32 %0, %1, %2;" : "=r"(r) : "f"(hi), "f"(lo));
    return r;
}

// ---------------- small kernels ----------------
__global__ void k_zero() {
    int i = blockIdx.x * blockDim.x + threadIdx.x;
    if (i < N_NODES) { g_deg[i] = 0.f; g_cnt[i] = 0; }
}

__global__ void k_deg(const int* __restrict__ ei, const float* __restrict__ ew) {
    int e = blockIdx.x * blockDim.x + threadIdx.x;
    if (e < N_EDGES) {
        int d = ei[N_EDGES + e];
        atomicAdd(&g_deg[d], ew[e]);
        atomicAdd(&g_cnt[d], 1);
    }
}

// exclusive scan of g_cnt + dinv (single block, 1024 threads)
__global__ void k_scan() {
    __shared__ int wsum[32];
    int t = threadIdx.x;
    int base = t * 4;
#pragma unroll
    for (int i = 0; i < 4; i++)
        g_dinv[base + i] = rsqrtf(g_deg[base + i] + 1.0f);  // self-loop weight 1
    int v[4];
#pragma unroll
    for (int i = 0; i < 4; i++) v[i] = g_cnt[base + i];
    int tot = v[0] + v[1] + v[2] + v[3];
    int lane = t & 31, w = t >> 5;
    int x = tot;
#pragma unroll
    for (int o = 1; o < 32; o <<= 1) {
        int y = __shfl_up_sync(0xffffffffu, x, o);
        if (lane >= o) x += y;
    }
    if (lane == 31) wsum[w] = x;
    __syncthreads();
    if (w == 0) {
        int y = wsum[lane];
#pragma unroll
        for (int o = 1; o < 32; o <<= 1) {
            int z = __shfl_up_sync(0xffffffffu, y, o);
            if (lane >= o) y += z;
        }
        wsum[lane] = y;
    }
    __syncthreads();
    int wbase = (w > 0) ? wsum[w - 1] : 0;
    int run = wbase + x - tot;   // exclusive prefix
#pragma unroll
    for (int i = 0; i < 4; i++) {
        g_rowptr[base + i] = run;
        g_cursor[base + i] = run;
        run += v[i];
    }
    if (t == 1023) g_rowptr[N_NODES] = run;
}

__global__ void k_fill(const int* __restrict__ ei) {
    int e = blockIdx.x * blockDim.x + threadIdx.x;
    if (e < N_EDGES) {
        int d = ei[N_EDGES + e];
        int p = atomicAdd(&g_cursor[d], 1);
        g_eidx[p] = e;
    }
}

// GCN aggregation: vectorized, 64 threads/node, float4 per thread
__global__ void k_gather(const float* __restrict__ h, const int* __restrict__ ei,
                         const float* __restrict__ ew, const float* __restrict__ bias,
                         float* __restrict__ out, int relu) {
    int n = blockIdx.x;
    int c4 = threadIdx.x;  // 64 threads, 4 channels each
    int beg = g_rowptr[n], end = g_rowptr[n + 1];
    float dn = g_dinv[n];
    const float4* h4 = (const float4*)h;
    float4 hv = h4[(size_t)n * (H / 4) + c4];
    float s = dn * dn;
    float4 acc = make_float4(s * hv.x, s * hv.y, s * hv.z, s * hv.w);
    __shared__ int   ssrc[64];
    __shared__ float scoef[64];
    for (int b0 = beg; b0 < end; b0 += 64) {
        int cnt = min(64, end - b0);
        if (c4 < cnt) {
            int e = g_eidx[b0 + c4];
            int sr = ei[e];
            ssrc[c4] = sr;
            scoef[c4] = g_dinv[sr] * ew[e] * dn;
        }
        __syncthreads();
        for (int i = 0; i < cnt; i++) {
            float co = scoef[i];
            float4 v = h4[(size_t)ssrc[i] * (H / 4) + c4];
            acc.x += co * v.x; acc.y += co * v.y;
            acc.z += co * v.z; acc.w += co * v.w;
        }
        __syncthreads();
    }
    float4 bz = ((const float4*)bias)[c4];
    acc.x += bz.x; acc.y += bz.y; acc.z += bz.z; acc.w += bz.w;
    if (relu) {
        acc.x = fmaxf(acc.x, 0.f); acc.y = fmaxf(acc.y, 0.f);
        acc.z = fmaxf(acc.z, 0.f); acc.w = fmaxf(acc.w, 0.f);
    }
    ((float4*)out)[(size_t)n * (H / 4) + c4] = acc;
}

// ---------------- tf32 tensor-core GEMM: pipelined, ldmatrix A+B fragment feed ----------------
// MA: A is the merged attention context computed on-the-fly from g_pacc/g_pm/g_pl
template <bool BT, int MODE, bool MA = false>
__global__ void __launch_bounds__(256) k_gemm_tf(const float* __restrict__ A,
                                                 const float* __restrict__ B,
                                                 const float* __restrict__ bias,
                                                 void* __restrict__ Cv,
                                                 int M, int Nn, int K) {
    __shared__ __align__(16) float As[2][128][20];  // [m][k], 80B stride
    __shared__ __align__(16) float Bs[2][64][20];   // [n][k], 80B stride
    const int tid = threadIdx.x;
    const int wid = tid >> 5, lane = tid & 31;
    const int wm = wid & 3, wn = wid >> 2;
    const int m0 = blockIdx.y * 128, n0 = blockIdx.x * 64;
    const int r = lane >> 2, c = lane & 3;

    const int a_row0 = tid >> 2, a_kq = tid & 3;
    const int a_row1 = a_row0 + 64;
    const int bt_n = tid >> 2, bt_kq = tid & 3;
    const int bn_k = tid >> 4, bn_nq = tid & 15;

    const int lm_row = (lane & 7) + ((lane >> 3) & 1) * 8;   // 0..15 (A tiles)
    const int lm_kof = (lane >> 4) << 2;                      // 0 or 4

    float acc[2][4][4];
#pragma unroll
    for (int mt = 0; mt < 2; mt++)
#pragma unroll
        for (int jn = 0; jn < 4; jn++)
#pragma unroll
            for (int i = 0; i < 4; i++) acc[mt][jn][i] = 0.f;

    const int nk = K >> 4;

    // merged-attention A element: row grow, channels col..col+3 (within one head)
    auto ldMA = [&](int grow, int col) -> float4 {
        int head = col >> 6, d = col & 63;
        int idx0 = (head * KSPLIT) * N_NODES + grow;
        int idx1 = idx0 + N_NODES;
        float pm0 = g_pm[idx0], pm1 = g_pm[idx1];
        float Mx = fmaxf(pm0, pm1);
        float w0 = __expf(pm0 - Mx), w1 = __expf(pm1 - Mx);
        float den = w0 * g_pl[idx0] + w1 * g_pl[idx1];
        float4 p0 = *(const float4*)(g_pacc + (size_t)idx0 * HD + d);
        float4 p1 = *(const float4*)(g_pacc + (size_t)idx1 * HD + d);
        float inv = 1.f / den;
        return make_float4((w0 * p0.x + w1 * p1.x) * inv,
                           (w0 * p0.y + w1 * p1.y) * inv,
                           (w0 * p0.z + w1 * p1.z) * inv,
                           (w0 * p0.w + w1 * p1.w) * inv);
    };

    auto ldA0 = [&](int k0) {
        if (MA) return ldMA(m0 + a_row0, k0 + 4 * a_kq);
        return *(const float4*)(A + (size_t)(m0 + a_row0) * K + k0 + 4 * a_kq);
    };
    auto ldA1 = [&](int k0) {
        if (MA) return ldMA(m0 + a_row1, k0 + 4 * a_kq);
        return *(const float4*)(A + (size_t)(m0 + a_row1) * K + k0 + 4 * a_kq);
    };
    auto ldB  = [&](int k0) {
        return BT ? *(const float4*)(B + (size_t)(n0 + bt_n) * K + k0 + 4 * bt_kq)
                  : *(const float4*)(B + (size_t)(k0 + bn_k) * Nn + n0 + 4 * bn_nq);
    };
    auto store = [&](int s, float4 va0, float4 va1, float4 vb) {
        *(float4*)&As[s][a_row0][4 * a_kq] = va0;    // direct copy, [m][k]
        *(float4*)&As[s][a_row1][4 * a_kq] = va1;
        if (BT) {
            *(float4*)&Bs[s][bt_n][4 * bt_kq] = vb;  // direct copy, [n][k]
        } else {
            // source row k, 4 consecutive n -> scatter to 4 [n][k] rows
            Bs[s][4 * bn_nq + 0][bn_k] = vb.x;
            Bs[s][4 * bn_nq + 1][bn_k] = vb.y;
            Bs[s][4 * bn_nq + 2][bn_k] = vb.z;
            Bs[s][4 * bn_nq + 3][bn_k] = vb.w;
        }
    };

    {
        float4 va0 = ldA0(0), va1 = ldA1(0), vb = ldB(0);
        store(0, va0, va1, vb);
    }
    __syncthreads();

    for (int kb = 0; kb < nk; kb++) {
        const int s = kb & 1;
        float4 va0, va1, vb;
        const bool more = (kb + 1 < nk);
        if (more) {
            int k0n = (kb + 1) << 4;
            va0 = ldA0(k0n); va1 = ldA1(k0n); vb = ldB(k0n);
        }

#pragma unroll
        for (int ks = 0; ks < 16; ks += 8) {
            unsigned a[2][4], b[4][2];
#pragma unroll
            for (int mt = 0; mt < 2; mt++) {
                int R = wm * 32 + mt * 16;
                ldm4(a[mt][0], a[mt][1], a[mt][2], a[mt][3],
                     sptr(&As[s][R + lm_row][ks + lm_kof]));
            }
            {
                unsigned t0, t1, t2, t3;
                ldm4(t0, t1, t2, t3, sptr(&Bs[s][wn * 32 + lane][ks]));
                b[0][0] = t0; b[1][0] = t1; b[2][0] = t2; b[3][0] = t3;
                ldm4(t0, t1, t2, t3, sptr(&Bs[s][wn * 32 + lane][ks + 4]));
                b[0][1] = t0; b[1][1] = t1; b[2][1] = t2; b[3][1] = t3;
            }
#pragma unroll
            for (int mt = 0; mt < 2; mt++)
#pragma unroll
                for (int jn = 0; jn < 4; jn++)
                    mma_tf32(acc[mt][jn], a[mt], b[jn]);
        }

        if (more) store(s ^ 1, va0, va1, vb);
        __syncthreads();
    }

    // epilogue
#pragma unroll
    for (int mt = 0; mt < 2; mt++) {
        int mrow0 = m0 + wm * 32 + mt * 16 + r;
#pragma unroll
        for (int jn = 0; jn < 4; jn++) {
            int col = n0 + wn * 32 + jn * 8 + 2 * c;
            float bz0 = bias ? bias[col] : 0.f;
            float bz1 = bias ? bias[col + 1] : 0.f;
            float v00 = acc[mt][jn][0] + bz0, v01 = acc[mt][jn][1] + bz1;
            float v10 = acc[mt][jn][2] + bz0, v11 = acc[mt][jn][3] + bz1;
            if (MODE == 1) {
                v00 = fmaxf(v00, 0.f); v01 = fmaxf(v01, 0.f);
                v10 = fmaxf(v10, 0.f); v11 = fmaxf(v11, 0.f);
            }
            if (MODE == 2) {
                float s = (col < H) ? 0.125f : 1.0f;  // Q pre-scale
                __nv_bfloat16* C = (__nv_bfloat16*)Cv;
                *(unsigned*)(C + (size_t)mrow0 * Nn + col) = packbf(v00 * s, v01 * s);
                *(unsigned*)(C + (size_t)(mrow0 + 8) * Nn + col) = packbf(v10 * s, v11 * s);
            } else {
                float* C = (float*)Cv;
                *(float2*)(C + (size_t)mrow0 * Nn + col) = make_float2(v00, v01);
                *(float2*)(C + (size_t)(mrow0 + 8) * Nn + col) = make_float2(v10, v11);
            }
        }
    }
}

// ---------------- attention: bf16 mma flash, cp.async double-buffered K/V ----------------
__global__ void __launch_bounds__(128) k_attn_mma(const __nv_bfloat16* __restrict__ qkvb) {
    __shared__ __align__(16) __nv_bfloat16 Qs[64 * 64];
    __shared__ __align__(16) __nv_bfloat16 Ks[2][64 * 64];
    __shared__ __align__(16) __nv_bfloat16 Vs[2][64 * 64];
    const int head = blockIdx.y, z = blockIdx.z;
    const int q0 = blockIdx.x * 64;
    const int t = threadIdx.x, w = t >> 5, lane = t & 31;
    const int r_in = lane & 7, mq = lane >> 3;
    const int NT = (N_NODES / KSPLIT) / 64;
    const int kbase = z * (N_NODES / KSPLIT);

    auto stageKV = [&](int s, int k0g) {
        int r = t >> 1, cb = (t & 1) * 4;
        size_t rb = (size_t)(k0g + r) * 768;
        const uint4* sk = (const uint4*)(qkvb + rb + 256 + head * 64);
        const uint4* sv = (const uint4*)(qkvb + rb + 512 + head * 64);
        uint4* dk = (uint4*)(Ks[s] + r * 64);
        uint4* dv = (uint4*)(Vs[s] + r * 64);
#pragma unroll
        for (int i = 0; i < 4; i++) {
            int c = cb + i;
            cpa16(sptr(dk + (c ^ (r & 7))), sk + c);
            cpa16(sptr(dv + (c ^ (r & 7))), sv + c);
        }
    };

    {
        int r = t >> 1, cb = (t & 1) * 4;
        const uint4* src = (const uint4*)(qkvb + (size_t)(q0 + r) * 768 + head * 64);
        uint4* dst = (uint4*)(Qs + r * 64);
#pragma unroll
        for (int i = 0; i < 4; i++) { int c = cb + i; dst[c ^ (r & 7)] = src[c]; }
    }
    stageKV(0, kbase);
    cpa_commit();
    __syncthreads();

    unsigned qf[4][4];
    {
        int row = 16 * w + (mq & 1) * 8 + r_in;
#pragma unroll
        for (int kk = 0; kk < 4; kk++) {
            int ch = 2 * kk + (mq >> 1);
            ldm4(qf[kk][0], qf[kk][1], qf[kk][2], qf[kk][3],
                 sptr(Qs + row * 64 + ((ch ^ (row & 7)) << 3)));
        }
    }

    float oacc[8][4];
#pragma unroll
    for (int j = 0; j < 8; j++)
#pragma unroll
        for (int i = 0; i < 4; i++) oacc[j][i] = 0.f;
    float m0 = -1e30f, m1 = -1e30f, l0 = 0.f, l1 = 0.f;

    for (int kt = 0; kt < NT; kt++) {
        const int s = kt & 1;
        if (kt + 1 < NT) stageKV(s ^ 1, kbase + (kt + 1) * 64);
        cpa_commit();
        cpa_wait1();
        __syncthreads();

        float sacc[8][4];
#pragma unroll
        for (int j = 0; j < 8; j++)
#pragma unroll
            for (int i = 0; i < 4; i++) sacc[j][i] = 0.f;
#pragma unroll
        for (int kk = 0; kk < 4; kk++) {
#pragma unroll
            for (int jp = 0; jp < 4; jp++) {
                unsigned b0, b1, b2, b3;
                int keyrow = 16 * jp + (mq >> 1) * 8 + r_in;
                int ch = 2 * kk + (mq & 1);
                ldm4(b0, b1, b2, b3, sptr(Ks[s] + keyrow * 64 + ((ch ^ (keyrow & 7)) << 3)));
                unsigned bb0[2] = {b0, b1}, bb1[2] = {b2, b3};
                mma_bf16(sacc[2 * jp], qf[kk], bb0);
                mma_bf16(sacc[2 * jp + 1], qf[kk], bb1);
            }
        }

        float tm0 = -1e30f, tm1 = -1e30f;
#pragma unroll
        for (int j = 0; j < 8; j++) {
            tm0 = fmaxf(tm0, fmaxf(sacc[j][0], sacc[j][1]));
            tm1 = fmaxf(tm1, fmaxf(sacc[j][2], sacc[j][3]));
        }
#pragma unroll
        for (int o = 1; o < 4; o <<= 1) {
            tm0 = fmaxf(tm0, __shfl_xor_sync(0xffffffffu, tm0, o));
            tm1 = fmaxf(tm1, __shfl_xor_sync(0xffffffffu, tm1, o));
        }
        float mn0 = fmaxf(m0, tm0), mn1 = fmaxf(m1, tm1);
        float c0 = __expf(m0 - mn0), c1 = __expf(m1 - mn1);
        l0 *= c0; l1 *= c1;
#pragma unroll
        for (int j = 0; j < 8; j++) {
            oacc[j][0] *= c0; oacc[j][1] *= c0;
            oacc[j][2] *= c1; oacc[j][3] *= c1;
        }
        unsigned pb[8][2];
#pragma unroll
        for (int j = 0; j < 8; j++) {
            float p0 = __expf(sacc[j][0] - mn0), p1 = __expf(sacc[j][1] - mn0);
            float p2 = __expf(sacc[j][2] - mn1), p3 = __expf(sacc[j][3] - mn1);
            l0 += p0 + p1; l1 += p2 + p3;
            pb[j][0] = packbf(p0, p1);
            pb[j][1] = packbf(p2, p3);
        }
        m0 = mn0; m1 = mn1;

#pragma unroll
        for (int kk = 0; kk < 4; kk++) {
            unsigned a[4] = {pb[2 * kk][0], pb[2 * kk][1], pb[2 * kk + 1][0], pb[2 * kk + 1][1]};
#pragma unroll
            for (int jp = 0; jp < 4; jp++) {
                unsigned b0, b1, b2, b3;
                int keyrow = 16 * kk + (mq & 1) * 8 + r_in;
                int ch = 2 * jp + (mq >> 1);
                ldm4t(b0, b1, b2, b3, sptr(Vs[s] + keyrow * 64 + ((ch ^ (keyrow & 7)) << 3)));
                unsigned bb0[2] = {b0, b1}, bb1[2] = {b2, b3};
                mma_bf16(oacc[2 * jp], a, bb0);
                mma_bf16(oacc[2 * jp + 1], a, bb1);
            }
        }
        __syncthreads();
    }

#pragma unroll
    for (int o = 1; o < 4; o <<= 1) {
        l0 += __shfl_xor_sync(0xffffffffu, l0, o);
        l1 += __shfl_xor_sync(0xffffffffu, l1, o);
    }
    int r = lane >> 2, cc = lane & 3;
    int row0 = q0 + 16 * w + r;
    int idx0 = (head * KSPLIT + z) * N_NODES + row0;
    int idx1 = idx0 + 8;
    float2* p0 = (float2*)(g_pacc + (size_t)idx0 * HD);
    float2* p1 = (float2*)(g_pacc + (size_t)idx1 * HD);
#pragma unroll
    for (int j = 0; j < 8; j++) {
        p0[4 * j + cc] = make_float2(oacc[j][0], oacc[j][1]);
        p1[4 * j + cc] = make_float2(oacc[j][2], oacc[j][3]);
    }
    if (cc == 0) {
        g_pm[idx0] = m0; g_pl[idx0] = l0;
        g_pm[idx1] = m1; g_pl[idx1] = l1;
    }
}

// out = (res ? res : 0) + LayerNorm(a + b) * g + beta
__global__ void k_ln(const float* __restrict__ a, const float* __restrict__ bb,
                     const float* __restrict__ g, const float* __restrict__ beta,
                     const float* __restrict__ res, float* __restrict__ out) {
    int n = blockIdx.x, t = threadIdx.x;  // 256
    float v = a[n * H + t] + bb[n * H + t];
    __shared__ float red[8];
    float s = v;
#pragma unroll
    for (int o = 16; o; o >>= 1) s += __shfl_xor_sync(0xffffffffu, s, o);
    if ((t & 31) == 0) red[t >> 5] = s;
    __syncthreads();
    float tot = 0.f;
#pragma unroll
    for (int i = 0; i < 8; i++) tot += red[i];
    float mean = tot * (1.f / H);
    float d = v - mean;
    float s2 = d * d;
#pragma unroll
    for (int o = 16; o; o >>= 1) s2 += __shfl_xor_sync(0xffffffffu, s2, o);
    __syncthreads();
    if ((t & 31) == 0) red[t >> 5] = s2;
    __syncthreads();
    float tot2 = 0.f;
#pragma unroll
    for (int i = 0; i < 8; i++) tot2 += red[i];
    float var = tot2 * (1.f / H);
    float o_ = d * rsqrtf(var + EPS) * g[t] + beta[t];
    if (res) o_ += res[n * H + t];
    out[n * H + t] = o_;
}

// classifier head + log_softmax (warp per row)
__global__ void k_cls(const float* __restrict__ xf, const float* __restrict__ W,
                      const float* __restrict__ b, float* __restrict__ out) {
    int n = blockIdx.x;
    int lane = threadIdx.x;  // 32
    float acc = -1e30f;
    if (lane < NCLS) {
        const float* xr = xf + (size_t)n * H;
        float a = 0.f;
        for (int k = 0; k < H; k++) a += xr[k] * W[k * NCLS + lane];
        acc = a + b[lane];
    }
    float mx = acc;
#pragma unroll
    for (int o = 8; o; o >>= 1) mx = fmaxf(mx, __shfl_xor_sync(0xffffffffu, mx, o, 16));
    float e = (lane < NCLS) ? __expf(acc - mx) : 0.f;
    float se = e;
#pragma unroll
    for (int o = 8; o; o >>= 1) se += __shfl_xor_sync(0xffffffffu, se, o, 16);
    if (lane < NCLS) out[n * NCLS + lane] = acc - mx - logf(se);
}

// decoder second layer + sigmoid (warp per row)
__global__ void k_d2(const float* __restrict__ d1, const float* __restrict__ W,
                     const float* __restrict__ b, float* __restrict__ out) {
    int n = blockIdx.x;
    int lane = threadIdx.x;
    const float* xr = d1 + (size_t)n * (2 * H);
    float a0 = 0.f, a1 = 0.f, a2 = 0.f;
    for (int k = lane; k < 2 * H; k += 32) {
        float xv = xr[k];
        a0 += xv * W[k * 3 + 0];
        a1 += xv * W[k * 3 + 1];
        a2 += xv * W[k * 3 + 2];
    }
#pragma unroll
    for (int o = 16; o; o >>= 1) {
        a0 += __shfl_xor_sync(0xffffffffu, a0, o);
        a1 += __shfl_xor_sync(0xffffffffu, a1, o);
        a2 += __shfl_xor_sync(0xffffffffu, a2, o);
    }
    if (lane == 0) {
        out[n * 3 + 0] = 1.f / (1.f + __expf(-(a0 + b[0])));
        out[n * 3 + 1] = 1.f / (1.f + __expf(-(a1 + b[1])));
        out[n * 3 + 2] = 1.f / (1.f + __expf(-(a2 + b[2])));
    }
}

// ---------------- launch ----------------
static float* symf(const void* sym) {
    void* p = nullptr;
    cudaGetSymbolAddress(&p, sym);
    return (float*)p;
}

extern "C" void kernel_launch(void* const* d_in, const int* in_sizes, int n_in,
                              void* d_out, int out_size) {
    const float* x        = (const float*)d_in[0];
    const int*   ei       = (const int*)d_in[1];
    const float* ea       = (const float*)d_in[2];
    const float* W_gcn1   = (const float*)d_in[3];
    const float* b_gcn1   = (const float*)d_in[4];
    const float* W_gcn2   = (const float*)d_in[5];
    const float* b_gcn2   = (const float*)d_in[6];
    const float* in_proj_w  = (const float*)d_in[7];
    const float* in_proj_b  = (const float*)d_in[8];
    const float* out_proj_w = (const float*)d_in[9];
    const float* out_proj_b = (const float*)d_in[10];
    const float* ln1_g    = (const float*)d_in[11];
    const float* ln1_b    = (const float*)d_in[12];
    const float* ffn_w1   = (const float*)d_in[13];
    const float* ffn_b1   = (const float*)d_in[14];
    const float* ffn_w2   = (const float*)d_in[15];
    const float* ffn_b2   = (const float*)d_in[16];
    const float* ln2_g    = (const float*)d_in[17];
    const float* ln2_b    = (const float*)d_in[18];
    const float* W_cls    = (const float*)d_in[19];
    const float* b_cls    = (const float*)d_in[20];
    const float* W_d1     = (const float*)d_in[21];
    const float* b_d1     = (const float*)d_in[22];
    const float* W_d2     = (const float*)d_in[23];
    const float* b_d2     = (const float*)d_in[24];

    float* out_cls  = (float*)d_out;
    float* out_reco = out_cls + (size_t)N_NODES * NCLS;

    float* p_h   = symf(g_h);
    float* p_g1  = symf(g_g1);
    float* p_xl  = symf(g_xl);
    float* p_x1  = symf(g_x1);
    float* p_ffn = symf(g_ffn);
    float* p_f2  = symf(g_f2);
    float* p_xf  = symf(g_xf);
    float* p_d1  = symf(g_d1);
    __nv_bfloat16* p_qkvb;
    { void* pp = nullptr; cudaGetSymbolAddress(&pp, g_qkvb); p_qkvb = (__nv_bfloat16*)pp; }

    // side stream + events (created once; no device memory involved)
    static cudaStream_t s2 = nullptr;
    static cudaEvent_t ev_fork1 = nullptr, ev_join1 = nullptr,
                       ev_fork2 = nullptr, ev_join2 = nullptr;
    if (!s2) {
        cudaStreamCreateWithFlags(&s2, cudaStreamNonBlocking);
        cudaEventCreateWithFlags(&ev_fork1, cudaEventDisableTiming);
        cudaEventCreateWithFlags(&ev_join1, cudaEventDisableTiming);
        cudaEventCreateWithFlags(&ev_fork2, cudaEventDisableTiming);
        cudaEventCreateWithFlags(&ev_join2, cudaEventDisableTiming);
    }

    // ---- fork 1: graph-structure build (s2) overlapped with GEMM1 (main) ----
    cudaEventRecord(ev_fork1, 0);
    cudaStreamWaitEvent(s2, ev_fork1, 0);

    k_zero<<<N_NODES / 256, 256, 0, s2>>>();
    k_deg<<<N_EDGES / 256, 256, 0, s2>>>(ei, ea);
    k_scan<<<1, 1024, 0, s2>>>();
    k_fill<<<N_EDGES / 256, 256, 0, s2>>>(ei);
    cudaEventRecord(ev_join1, s2);

    // GCN layer 1 GEMM: h = x @ W1 (independent of edge structure)
    k_gemm_tf<false, 0><<<dim3(H / 64, N_NODES / 128), 256>>>(x, W_gcn1, nullptr, p_h,
                                                              N_NODES, H, IN_CH);
    cudaStreamWaitEvent(0, ev_join1, 0);

    k_gather<<<N_NODES, 64>>>(p_h, ei, ea, b_gcn1, p_g1, 1);

    // GCN layer 2
    k_gemm_tf<false, 0><<<dim3(H / 64, N_NODES / 128), 256>>>(p_g1, W_gcn2, nullptr, p_h,
                                                              N_NODES, H, H);
    k_gather<<<N_NODES, 64>>>(p_h, ei, ea, b_gcn2, p_xl, 0);

    // QKV projection (B transposed) -> bf16 qkv directly (Q pre-scaled)
    k_gemm_tf<true, 2><<<dim3(3 * H / 64, N_NODES / 128), 256>>>(p_xl, in_proj_w, in_proj_b,
                                                                 p_qkvb, N_NODES, 3 * H, H);

    // attention (bf16 tensor-core flash, cp.async pipelined K/V)
    k_attn_mma<<<dim3(N_NODES / 64, NHEAD, KSPLIT), 128>>>(p_qkvb);

    // out projection with fused split-K merge (A computed from g_pacc/g_pm/g_pl)
    k_gemm_tf<true, 0, true><<<dim3(H / 64, N_NODES / 128), 256>>>(nullptr, out_proj_w,
                                                                   out_proj_b, p_h,
                                                                   N_NODES, H, H);

    // x1 = LN(x_local + attn_out)
    k_ln<<<N_NODES, H>>>(p_xl, p_h, ln1_g, ln1_b, nullptr, p_x1);

    // FFN
    k_gemm_tf<false, 1><<<dim3(4 * H / 64, N_NODES / 128), 256>>>(p_x1, ffn_w1, ffn_b1,
                                                                  p_ffn, N_NODES, 4 * H, H);
    k_gemm_tf<false, 0><<<dim3(H / 64, N_NODES / 128), 256>>>(p_ffn, ffn_w2, ffn_b2,
                                                              p_f2, N_NODES, H, 4 * H);

    // x_final = x_local + LN(x1 + ffn_out)
    k_ln<<<N_NODES, H>>>(p_x1, p_f2, ln2_g, ln2_b, p_xl, p_xf);

    // ---- fork 2: decoder branch (s2) overlapped with classifier (main) ----
    cudaEventRecord(ev_fork2, 0);
    cudaStreamWaitEvent(s2, ev_fork2, 0);

    k_gemm_tf<false, 1><<<dim3(2 * H / 64, N_NODES / 128), 256, 0, s2>>>(p_xf, W_d1, b_d1,
                                                                         p_d1, N_NODES, 2 * H, H);
    k_d2<<<N_NODES, 32, 0, s2>>>(p_d1, W_d2, b_d2, out_reco);
    cudaEventRecord(ev_join2, s2);

    k_cls<<<N_NODES, 32>>>(p_xf, W_cls, b_cls, out_cls);
    cudaStreamWaitEvent(0, ev_join2, 0);
}

// round 16
// speedup vs baseline: 1.0702x; 1.0702x over previous
#include <cuda_runtime.h>
#include <cuda_bf16.h>
#include <math.h>

#define N_NODES 4096
#define N_EDGES 131072
#define IN_CH   128
#define H       256
#define NCLS    16
#define NHEAD   4
#define HD      64
#define KSPLIT  2
#define MAXD    128
#define EPS     1e-5f

// ---------------- device scratch (static, no allocs) ----------------
__device__ float g_deg[N_NODES];
__device__ int   g_cnt[N_NODES];
__device__ int   g_eidx[N_NODES * MAXD];

__device__ __align__(16) float g_h   [N_NODES * H];       // gemm scratch
__device__ __align__(16) float g_g1  [N_NODES * H];       // gcn1 out (relu)
__device__ __align__(16) float g_xl  [N_NODES * H];       // x_local
__device__ __align__(16) __nv_bfloat16 g_qkvb[N_NODES * 3 * H];  // bf16 QKV (Q pre-scaled)
__device__ __align__(16) float g_x1  [N_NODES * H];       // after ln1
__device__ __align__(16) float g_ffn [N_NODES * 4 * H];
__device__ __align__(16) float g_f2  [N_NODES * H];
__device__ __align__(16) float g_xf  [N_NODES * H];       // x_final
__device__ __align__(16) float g_d1  [N_NODES * 2 * H];
__device__ __align__(16) float g_pacc[NHEAD * KSPLIT * N_NODES * HD];
__device__ float g_pm[NHEAD * KSPLIT * N_NODES];
__device__ float g_pl[NHEAD * KSPLIT * N_NODES];

// ---------------- asm helpers ----------------
__device__ __forceinline__ unsigned sptr(const void* p) {
    return (unsigned)__cvta_generic_to_shared(p);
}
__device__ __forceinline__ void cpa16(unsigned dst, const void* src) {
    asm volatile("cp.async.ca.shared.global [%0], [%1], 16;" :: "r"(dst), "l"(src));
}
__device__ __forceinline__ void cpa_commit() {
    asm volatile("cp.async.commit_group;");
}
__device__ __forceinline__ void cpa_wait1() {
    asm volatile("cp.async.wait_group 1;");
}
__device__ __forceinline__ void ldm4(unsigned& r0, unsigned& r1, unsigned& r2, unsigned& r3,
                                     unsigned addr) {
    asm volatile("ldmatrix.sync.aligned.m8n8.x4.shared.b16 {%0,%1,%2,%3},[%4];"
                 : "=r"(r0), "=r"(r1), "=r"(r2), "=r"(r3) : "r"(addr));
}
__device__ __forceinline__ void ldm4t(unsigned& r0, unsigned& r1, unsigned& r2, unsigned& r3,
                                      unsigned addr) {
    asm volatile("ldmatrix.sync.aligned.m8n8.x4.trans.shared.b16 {%0,%1,%2,%3},[%4];"
                 : "=r"(r0), "=r"(r1), "=r"(r2), "=r"(r3) : "r"(addr));
}
__device__ __forceinline__ void mma_bf16(float* d, const unsigned* a, const unsigned* b) {
    asm volatile("mma.sync.aligned.m16n8k16.row.col.f32.bf16.bf16.f32 "
                 "{%0,%1,%2,%3},{%4,%5,%6,%7},{%8,%9},{%0,%1,%2,%3};"
                 : "+f"(d[0]), "+f"(d[1]), "+f"(d[2]), "+f"(d[3])
                 : "r"(a[0]), "r"(a[1]), "r"(a[2]), "r"(a[3]), "r"(b[0]), "r"(b[1]));
}
__device__ __forceinline__ void mma_tf32(float* d, const unsigned* a, const unsigned* b) {
    asm volatile("mma.sync.aligned.m16n8k8.row.col.f32.tf32.tf32.f32 "
                 "{%0,%1,%2,%3},{%4,%5,%6,%7},{%8,%9},{%0,%1,%2,%3};"
                 : "+f"(d[0]), "+f"(d[1]), "+f"(d[2]), "+f"(d[3])
                 : "r"(a[0]), "r"(a[1]), "r"(a[2]), "r"(a[3]), "r"(b[0]), "r"(b[1]));
}
__device__ __forceinline__ unsigned packbf(float lo, float hi) {
    unsigned r;
    asm("cvt.rn.bf16x2.f32 %0, %1, %2;" : "=r"(r) : "f"(hi), "f"(lo));
    return r;
}

// ---------------- setup kernels ----------------
__global__ void k_zero() {
    int i = blockIdx.x * blockDim.x + threadIdx.x;
    if (i < N_NODES) { g_deg[i] = 0.f; g_cnt[i] = 0; }
}

// single pass: accumulate weighted degree AND bucket-fill edge ids
__global__ void k_degfill(const int* __restrict__ ei, const float* __restrict__ ew) {
    int e = blockIdx.x * blockDim.x + threadIdx.x;
    if (e < N_EDGES) {
        int d = ei[N_EDGES + e];
        atomicAdd(&g_deg[d], ew[e]);
        int pos = atomicAdd(&g_cnt[d], 1);
        if (pos < MAXD) g_eidx[d * MAXD + pos] = e;
    }
}

// GCN aggregation: vectorized, 64 threads/node, float4 per thread; dinv on the fly
__global__ void k_gather(const float* __restrict__ h, const int* __restrict__ ei,
                         const float* __restrict__ ew, const float* __restrict__ bias,
                         float* __restrict__ out, int relu) {
    int n = blockIdx.x;
    int c4 = threadIdx.x;  // 64 threads, 4 channels each
    int cnt_n = min(g_cnt[n], MAXD);
    float dn = rsqrtf(g_deg[n] + 1.0f);   // self-loop weight 1
    const float4* h4 = (const float4*)h;
    float4 hv = h4[(size_t)n * (H / 4) + c4];
    float s = dn * dn;
    float4 acc = make_float4(s * hv.x, s * hv.y, s * hv.z, s * hv.w);
    __shared__ int   ssrc[64];
    __shared__ float scoef[64];
    const int base = n * MAXD;
    for (int b0 = 0; b0 < cnt_n; b0 += 64) {
        int cnt = min(64, cnt_n - b0);
        if (c4 < cnt) {
            int e = g_eidx[base + b0 + c4];
            int sr = ei[e];
            ssrc[c4] = sr;
            scoef[c4] = rsqrtf(g_deg[sr] + 1.0f) * ew[e] * dn;
        }
        __syncthreads();
        for (int i = 0; i < cnt; i++) {
            float co = scoef[i];
            float4 v = h4[(size_t)ssrc[i] * (H / 4) + c4];
            acc.x += co * v.x; acc.y += co * v.y;
            acc.z += co * v.z; acc.w += co * v.w;
        }
        __syncthreads();
    }
    float4 bz = ((const float4*)bias)[c4];
    acc.x += bz.x; acc.y += bz.y; acc.z += bz.z; acc.w += bz.w;
    if (relu) {
        acc.x = fmaxf(acc.x, 0.f); acc.y = fmaxf(acc.y, 0.f);
        acc.z = fmaxf(acc.z, 0.f); acc.w = fmaxf(acc.w, 0.f);
    }
    ((float4*)out)[(size_t)n * (H / 4) + c4] = acc;
}

// ---------------- tf32 tensor-core GEMM: pipelined, ldmatrix A-fragment feed ----------------
// MA: A is the merged attention context computed on-the-fly from g_pacc/g_pm/g_pl
template <bool BT, int MODE, bool MA = false>
__global__ void __launch_bounds__(256) k_gemm_tf(const float* __restrict__ A,
                                                 const float* __restrict__ B,
                                                 const float* __restrict__ bias,
                                                 void* __restrict__ Cv,
                                                 int M, int Nn, int K) {
    __shared__ __align__(16) float As[2][128][20];  // [m][k], 80B stride
    __shared__ unsigned Bs[2][16][72];              // [k][n], pad 8
    const int tid = threadIdx.x;
    const int wid = tid >> 5, lane = tid & 31;
    const int wm = wid & 3, wn = wid >> 2;
    const int m0 = blockIdx.y * 128, n0 = blockIdx.x * 64;
    const int r = lane >> 2, c = lane & 3;

    const int a_row0 = tid >> 2, a_kq = tid & 3;
    const int a_row1 = a_row0 + 64;
    const int bt_n = tid >> 2, bt_kq = tid & 3;
    const int bn_k = tid >> 4, bn_nq = tid & 15;

    const int lm_row = (lane & 7) + ((lane >> 3) & 1) * 8;   // 0..15
    const int lm_kof = (lane >> 4) << 2;                      // 0 or 4

    float acc[2][4][4];
#pragma unroll
    for (int mt = 0; mt < 2; mt++)
#pragma unroll
        for (int jn = 0; jn < 4; jn++)
#pragma unroll
            for (int i = 0; i < 4; i++) acc[mt][jn][i] = 0.f;

    const int nk = K >> 4;

    // merged-attention A element: row grow, channels col..col+3 (within one head)
    auto ldMA = [&](int grow, int col) -> float4 {
        int head = col >> 6, d = col & 63;
        int idx0 = (head * KSPLIT) * N_NODES + grow;
        int idx1 = idx0 + N_NODES;
        float pm0 = g_pm[idx0], pm1 = g_pm[idx1];
        float Mx = fmaxf(pm0, pm1);
        float w0 = __expf(pm0 - Mx), w1 = __expf(pm1 - Mx);
        float den = w0 * g_pl[idx0] + w1 * g_pl[idx1];
        float4 p0 = *(const float4*)(g_pacc + (size_t)idx0 * HD + d);
        float4 p1 = *(const float4*)(g_pacc + (size_t)idx1 * HD + d);
        float inv = 1.f / den;
        return make_float4((w0 * p0.x + w1 * p1.x) * inv,
                           (w0 * p0.y + w1 * p1.y) * inv,
                           (w0 * p0.z + w1 * p1.z) * inv,
                           (w0 * p0.w + w1 * p1.w) * inv);
    };

    auto ldA0 = [&](int k0) {
        if (MA) return ldMA(m0 + a_row0, k0 + 4 * a_kq);
        return *(const float4*)(A + (size_t)(m0 + a_row0) * K + k0 + 4 * a_kq);
    };
    auto ldA1 = [&](int k0) {
        if (MA) return ldMA(m0 + a_row1, k0 + 4 * a_kq);
        return *(const float4*)(A + (size_t)(m0 + a_row1) * K + k0 + 4 * a_kq);
    };
    auto ldB  = [&](int k0) {
        return BT ? *(const float4*)(B + (size_t)(n0 + bt_n) * K + k0 + 4 * bt_kq)
                  : *(const float4*)(B + (size_t)(k0 + bn_k) * Nn + n0 + 4 * bn_nq);
    };
    auto store = [&](int s, float4 va0, float4 va1, float4 vb) {
        *(float4*)&As[s][a_row0][4 * a_kq] = va0;    // direct copy, [m][k]
        *(float4*)&As[s][a_row1][4 * a_kq] = va1;
        if (BT) {
            Bs[s][4 * bt_kq + 0][bt_n] = __float_as_uint(vb.x);
            Bs[s][4 * bt_kq + 1][bt_n] = __float_as_uint(vb.y);
            Bs[s][4 * bt_kq + 2][bt_n] = __float_as_uint(vb.z);
            Bs[s][4 * bt_kq + 3][bt_n] = __float_as_uint(vb.w);
        } else {
            Bs[s][bn_k][4 * bn_nq + 0] = __float_as_uint(vb.x);
            Bs[s][bn_k][4 * bn_nq + 1] = __float_as_uint(vb.y);
            Bs[s][bn_k][4 * bn_nq + 2] = __float_as_uint(vb.z);
            Bs[s][bn_k][4 * bn_nq + 3] = __float_as_uint(vb.w);
        }
    };

    {
        float4 va0 = ldA0(0), va1 = ldA1(0), vb = ldB(0);
        store(0, va0, va1, vb);
    }
    __syncthreads();

    for (int kb = 0; kb < nk; kb++) {
        const int s = kb & 1;
        float4 va0, va1, vb;
        const bool more = (kb + 1 < nk);
        if (more) {
            int k0n = (kb + 1) << 4;
            va0 = ldA0(k0n); va1 = ldA1(k0n); vb = ldB(k0n);
        }

#pragma unroll
        for (int ks = 0; ks < 16; ks += 8) {
            unsigned a[2][4], b[4][2];
#pragma unroll
            for (int mt = 0; mt < 2; mt++) {
                int R = wm * 32 + mt * 16;
                ldm4(a[mt][0], a[mt][1], a[mt][2], a[mt][3],
                     sptr(&As[s][R + lm_row][ks + lm_kof]));
            }
#pragma unroll
            for (int jn = 0; jn < 4; jn++) {
                int col = wn * 32 + jn * 8 + r;
                b[jn][0] = Bs[s][ks + c][col];
                b[jn][1] = Bs[s][ks + 4 + c][col];
            }
#pragma unroll
            for (int mt = 0; mt < 2; mt++)
#pragma unroll
                for (int jn = 0; jn < 4; jn++)
                    mma_tf32(acc[mt][jn], a[mt], b[jn]);
        }

        if (more) store(s ^ 1, va0, va1, vb);
        __syncthreads();
    }

    // epilogue
#pragma unroll
    for (int mt = 0; mt < 2; mt++) {
        int mrow0 = m0 + wm * 32 + mt * 16 + r;
#pragma unroll
        for (int jn = 0; jn < 4; jn++) {
            int col = n0 + wn * 32 + jn * 8 + 2 * c;
            float bz0 = bias ? bias[col] : 0.f;
            float bz1 = bias ? bias[col + 1] : 0.f;
            float v00 = acc[mt][jn][0] + bz0, v01 = acc[mt][jn][1] + bz1;
            float v10 = acc[mt][jn][2] + bz0, v11 = acc[mt][jn][3] + bz1;
            if (MODE == 1) {
                v00 = fmaxf(v00, 0.f); v01 = fmaxf(v01, 0.f);
                v10 = fmaxf(v10, 0.f); v11 = fmaxf(v11, 0.f);
            }
            if (MODE == 2) {
                float s = (col < H) ? 0.125f : 1.0f;  // Q pre-scale
                __nv_bfloat16* C = (__nv_bfloat16*)Cv;
                *(unsigned*)(C + (size_t)mrow0 * Nn + col) = packbf(v00 * s, v01 * s);
                *(unsigned*)(C + (size_t)(mrow0 + 8) * Nn + col) = packbf(v10 * s, v11 * s);
            } else {
                float* C = (float*)Cv;
                *(float2*)(C + (size_t)mrow0 * Nn + col) = make_float2(v00, v01);
                *(float2*)(C + (size_t)(mrow0 + 8) * Nn + col) = make_float2(v10, v11);
            }
        }
    }
}

// ---------------- attention: bf16 mma flash, cp.async double-buffered K/V ----------------
__global__ void __launch_bounds__(128) k_attn_mma(const __nv_bfloat16* __restrict__ qkvb) {
    __shared__ __align__(16) __nv_bfloat16 Qs[64 * 64];
    __shared__ __align__(16) __nv_bfloat16 Ks[2][64 * 64];
    __shared__ __align__(16) __nv_bfloat16 Vs[2][64 * 64];
    const int head = blockIdx.y, z = blockIdx.z;
    const int q0 = blockIdx.x * 64;
    const int t = threadIdx.x, w = t >> 5, lane = t & 31;
    const int r_in = lane & 7, mq = lane >> 3;
    const int NT = (N_NODES / KSPLIT) / 64;
    const int kbase = z * (N_NODES / KSPLIT);

    auto stageKV = [&](int s, int k0g) {
        int r = t >> 1, cb = (t & 1) * 4;
        size_t rb = (size_t)(k0g + r) * 768;
        const uint4* sk = (const uint4*)(qkvb + rb + 256 + head * 64);
        const uint4* sv = (const uint4*)(qkvb + rb + 512 + head * 64);
        uint4* dk = (uint4*)(Ks[s] + r * 64);
        uint4* dv = (uint4*)(Vs[s] + r * 64);
#pragma unroll
        for (int i = 0; i < 4; i++) {
            int c = cb + i;
            cpa16(sptr(dk + (c ^ (r & 7))), sk + c);
            cpa16(sptr(dv + (c ^ (r & 7))), sv + c);
        }
    };

    {
        int r = t >> 1, cb = (t & 1) * 4;
        const uint4* src = (const uint4*)(qkvb + (size_t)(q0 + r) * 768 + head * 64);
        uint4* dst = (uint4*)(Qs + r * 64);
#pragma unroll
        for (int i = 0; i < 4; i++) { int c = cb + i; dst[c ^ (r & 7)] = src[c]; }
    }
    stageKV(0, kbase);
    cpa_commit();
    __syncthreads();

    unsigned qf[4][4];
    {
        int row = 16 * w + (mq & 1) * 8 + r_in;
#pragma unroll
        for (int kk = 0; kk < 4; kk++) {
            int ch = 2 * kk + (mq >> 1);
            ldm4(qf[kk][0], qf[kk][1], qf[kk][2], qf[kk][3],
                 sptr(Qs + row * 64 + ((ch ^ (row & 7)) << 3)));
        }
    }

    float oacc[8][4];
#pragma unroll
    for (int j = 0; j < 8; j++)
#pragma unroll
        for (int i = 0; i < 4; i++) oacc[j][i] = 0.f;
    float m0 = -1e30f, m1 = -1e30f, l0 = 0.f, l1 = 0.f;

    for (int kt = 0; kt < NT; kt++) {
        const int s = kt & 1;
        if (kt + 1 < NT) stageKV(s ^ 1, kbase + (kt + 1) * 64);
        cpa_commit();
        cpa_wait1();
        __syncthreads();

        float sacc[8][4];
#pragma unroll
        for (int j = 0; j < 8; j++)
#pragma unroll
            for (int i = 0; i < 4; i++) sacc[j][i] = 0.f;
#pragma unroll
        for (int kk = 0; kk < 4; kk++) {
#pragma unroll
            for (int jp = 0; jp < 4; jp++) {
                unsigned b0, b1, b2, b3;
                int keyrow = 16 * jp + (mq >> 1) * 8 + r_in;
                int ch = 2 * kk + (mq & 1);
                ldm4(b0, b1, b2, b3, sptr(Ks[s] + keyrow * 64 + ((ch ^ (keyrow & 7)) << 3)));
                unsigned bb0[2] = {b0, b1}, bb1[2] = {b2, b3};
                mma_bf16(sacc[2 * jp], qf[kk], bb0);
                mma_bf16(sacc[2 * jp + 1], qf[kk], bb1);
            }
        }

        float tm0 = -1e30f, tm1 = -1e30f;
#pragma unroll
        for (int j = 0; j < 8; j++) {
            tm0 = fmaxf(tm0, fmaxf(sacc[j][0], sacc[j][1]));
            tm1 = fmaxf(tm1, fmaxf(sacc[j][2], sacc[j][3]));
        }
#pragma unroll
        for (int o = 1; o < 4; o <<= 1) {
            tm0 = fmaxf(tm0, __shfl_xor_sync(0xffffffffu, tm0, o));
            tm1 = fmaxf(tm1, __shfl_xor_sync(0xffffffffu, tm1, o));
        }
        float mn0 = fmaxf(m0, tm0), mn1 = fmaxf(m1, tm1);
        float c0 = __expf(m0 - mn0), c1 = __expf(m1 - mn1);
        l0 *= c0; l1 *= c1;
#pragma unroll
        for (int j = 0; j < 8; j++) {
            oacc[j][0] *= c0; oacc[j][1] *= c0;
            oacc[j][2] *= c1; oacc[j][3] *= c1;
        }
        unsigned pb[8][2];
#pragma unroll
        for (int j = 0; j < 8; j++) {
            float p0 = __expf(sacc[j][0] - mn0), p1 = __expf(sacc[j][1] - mn0);
            float p2 = __expf(sacc[j][2] - mn1), p3 = __expf(sacc[j][3] - mn1);
            l0 += p0 + p1; l1 += p2 + p3;
            pb[j][0] = packbf(p0, p1);
            pb[j][1] = packbf(p2, p3);
        }
        m0 = mn0; m1 = mn1;

#pragma unroll
        for (int kk = 0; kk < 4; kk++) {
            unsigned a[4] = {pb[2 * kk][0], pb[2 * kk][1], pb[2 * kk + 1][0], pb[2 * kk + 1][1]};
#pragma unroll
            for (int jp = 0; jp < 4; jp++) {
                unsigned b0, b1, b2, b3;
                int keyrow = 16 * kk + (mq & 1) * 8 + r_in;
                int ch = 2 * jp + (mq >> 1);
                ldm4t(b0, b1, b2, b3, sptr(Vs[s] + keyrow * 64 + ((ch ^ (keyrow & 7)) << 3)));
                unsigned bb0[2] = {b0, b1}, bb1[2] = {b2, b3};
                mma_bf16(oacc[2 * jp], a, bb0);
                mma_bf16(oacc[2 * jp + 1], a, bb1);
            }
        }
        __syncthreads();
    }

#pragma unroll
    for (int o = 1; o < 4; o <<= 1) {
        l0 += __shfl_xor_sync(0xffffffffu, l0, o);
        l1 += __shfl_xor_sync(0xffffffffu, l1, o);
    }
    int r = lane >> 2, cc = lane & 3;
    int row0 = q0 + 16 * w + r;
    int idx0 = (head * KSPLIT + z) * N_NODES + row0;
    int idx1 = idx0 + 8;
    float2* p0 = (float2*)(g_pacc + (size_t)idx0 * HD);
    float2* p1 = (float2*)(g_pacc + (size_t)idx1 * HD);
#pragma unroll
    for (int j = 0; j < 8; j++) {
        p0[4 * j + cc] = make_float2(oacc[j][0], oacc[j][1]);
        p1[4 * j + cc] = make_float2(oacc[j][2], oacc[j][3]);
    }
    if (cc == 0) {
        g_pm[idx0] = m0; g_pl[idx0] = l0;
        g_pm[idx1] = m1; g_pl[idx1] = l1;
    }
}

// out = (res ? res : 0) + LayerNorm(a + b) * g + beta
__global__ void k_ln(const float* __restrict__ a, const float* __restrict__ bb,
                     const float* __restrict__ g, const float* __restrict__ beta,
                     const float* __restrict__ res, float* __restrict__ out) {
    int n = blockIdx.x, t = threadIdx.x;  // 256
    float v = a[n * H + t] + bb[n * H + t];
    __shared__ float red[8];
    float s = v;
#pragma unroll
    for (int o = 16; o; o >>= 1) s += __shfl_xor_sync(0xffffffffu, s, o);
    if ((t & 31) == 0) red[t >> 5] = s;
    __syncthreads();
    float tot = 0.f;
#pragma unroll
    for (int i = 0; i < 8; i++) tot += red[i];
    float mean = tot * (1.f / H);
    float d = v - mean;
    float s2 = d * d;
#pragma unroll
    for (int o = 16; o; o >>= 1) s2 += __shfl_xor_sync(0xffffffffu, s2, o);
    __syncthreads();
    if ((t & 31) == 0) red[t >> 5] = s2;
    __syncthreads();
    float tot2 = 0.f;
#pragma unroll
    for (int i = 0; i < 8; i++) tot2 += red[i];
    float var = tot2 * (1.f / H);
    float o_ = d * rsqrtf(var + EPS) * g[t] + beta[t];
    if (res) o_ += res[n * H + t];
    out[n * H + t] = o_;
}

// classifier head + log_softmax (warp per row)
__global__ void k_cls(const float* __restrict__ xf, const float* __restrict__ W,
                      const float* __restrict__ b, float* __restrict__ out) {
    int n = blockIdx.x;
    int lane = threadIdx.x;  // 32
    float acc = -1e30f;
    if (lane < NCLS) {
        const float* xr = xf + (size_t)n * H;
        float a = 0.f;
        for (int k = 0; k < H; k++) a += xr[k] * W[k * NCLS + lane];
        acc = a + b[lane];
    }
    float mx = acc;
#pragma unroll
    for (int o = 8; o; o >>= 1) mx = fmaxf(mx, __shfl_xor_sync(0xffffffffu, mx, o, 16));
    float e = (lane < NCLS) ? __expf(acc - mx) : 0.f;
    float se = e;
#pragma unroll
    for (int o = 8; o; o >>= 1) se += __shfl_xor_sync(0xffffffffu, se, o, 16);
    if (lane < NCLS) out[n * NCLS + lane] = acc - mx - logf(se);
}

// decoder second layer + sigmoid (warp per row)
__global__ void k_d2(const float* __restrict__ d1, const float* __restrict__ W,
                     const float* __restrict__ b, float* __restrict__ out) {
    int n = blockIdx.x;
    int lane = threadIdx.x;
    const float* xr = d1 + (size_t)n * (2 * H);
    float a0 = 0.f, a1 = 0.f, a2 = 0.f;
    for (int k = lane; k < 2 * H; k += 32) {
        float xv = xr[k];
        a0 += xv * W[k * 3 + 0];
        a1 += xv * W[k * 3 + 1];
        a2 += xv * W[k * 3 + 2];
    }
#pragma unroll
    for (int o = 16; o; o >>= 1) {
        a0 += __shfl_xor_sync(0xffffffffu, a0, o);
        a1 += __shfl_xor_sync(0xffffffffu, a1, o);
        a2 += __shfl_xor_sync(0xffffffffu, a2, o);
    }
    if (lane == 0) {
        out[n * 3 + 0] = 1.f / (1.f + __expf(-(a0 + b[0])));
        out[n * 3 + 1] = 1.f / (1.f + __expf(-(a1 + b[1])));
        out[n * 3 + 2] = 1.f / (1.f + __expf(-(a2 + b[2])));
    }
}

// ---------------- launch ----------------
static float* symf(const void* sym) {
    void* p = nullptr;
    cudaGetSymbolAddress(&p, sym);
    return (float*)p;
}

extern "C" void kernel_launch(void* const* d_in, const int* in_sizes, int n_in,
                              void* d_out, int out_size) {
    const float* x        = (const float*)d_in[0];
    const int*   ei       = (const int*)d_in[1];
    const float* ea       = (const float*)d_in[2];
    const float* W_gcn1   = (const float*)d_in[3];
    const float* b_gcn1   = (const float*)d_in[4];
    const float* W_gcn2   = (const float*)d_in[5];
    const float* b_gcn2   = (const float*)d_in[6];
    const float* in_proj_w  = (const float*)d_in[7];
    const float* in_proj_b  = (const float*)d_in[8];
    const float* out_proj_w = (const float*)d_in[9];
    const float* out_proj_b = (const float*)d_in[10];
    const float* ln1_g    = (const float*)d_in[11];
    const float* ln1_b    = (const float*)d_in[12];
    const float* ffn_w1   = (const float*)d_in[13];
    const float* ffn_b1   = (const float*)d_in[14];
    const float* ffn_w2   = (const float*)d_in[15];
    const float* ffn_b2   = (const float*)d_in[16];
    const float* ln2_g    = (const float*)d_in[17];
    const float* ln2_b    = (const float*)d_in[18];
    const float* W_cls    = (const float*)d_in[19];
    const float* b_cls    = (const float*)d_in[20];
    const float* W_d1     = (const float*)d_in[21];
    const float* b_d1     = (const float*)d_in[22];
    const float* W_d2     = (const float*)d_in[23];
    const float* b_d2     = (const float*)d_in[24];

    float* out_cls  = (float*)d_out;
    float* out_reco = out_cls + (size_t)N_NODES * NCLS;

    float* p_h   = symf(g_h);
    float* p_g1  = symf(g_g1);
    float* p_xl  = symf(g_xl);
    float* p_x1  = symf(g_x1);
    float* p_ffn = symf(g_ffn);
    float* p_f2  = symf(g_f2);
    float* p_xf  = symf(g_xf);
    float* p_d1  = symf(g_d1);
    __nv_bfloat16* p_qkvb;
    { void* pp = nullptr; cudaGetSymbolAddress(&pp, g_qkvb); p_qkvb = (__nv_bfloat16*)pp; }

    // side stream + events (created once; no device memory involved)
    static cudaStream_t s2 = nullptr;
    static cudaEvent_t ev_fork1 = nullptr, ev_join1 = nullptr,
                       ev_fork2 = nullptr, ev_join2 = nullptr;
    if (!s2) {
        cudaStreamCreateWithFlags(&s2, cudaStreamNonBlocking);
        cudaEventCreateWithFlags(&ev_fork1, cudaEventDisableTiming);
        cudaEventCreateWithFlags(&ev_join1, cudaEventDisableTiming);
        cudaEventCreateWithFlags(&ev_fork2, cudaEventDisableTiming);
        cudaEventCreateWithFlags(&ev_join2, cudaEventDisableTiming);
    }

    // ---- fork 1: graph-structure build (s2) overlapped with GEMM1 (main) ----
    cudaEventRecord(ev_fork1, 0);
    cudaStreamWaitEvent(s2, ev_fork1, 0);

    k_zero<<<N_NODES / 256, 256, 0, s2>>>();
    k_degfill<<<N_EDGES / 256, 256, 0, s2>>>(ei, ea);
    cudaEventRecord(ev_join1, s2);

    // GCN layer 1 GEMM: h = x @ W1 (independent of edge structure)
    k_gemm_tf<false, 0><<<dim3(H / 64, N_NODES / 128), 256>>>(x, W_gcn1, nullptr, p_h,
                                                              N_NODES, H, IN_CH);
    cudaStreamWaitEvent(0, ev_join1, 0);

    k_gather<<<N_NODES, 64>>>(p_h, ei, ea, b_gcn1, p_g1, 1);

    // GCN layer 2
    k_gemm_tf<false, 0><<<dim3(H / 64, N_NODES / 128), 256>>>(p_g1, W_gcn2, nullptr, p_h,
                                                              N_NODES, H, H);
    k_gather<<<N_NODES, 64>>>(p_h, ei, ea, b_gcn2, p_xl, 0);

    // QKV projection (B transposed) -> bf16 qkv directly (Q pre-scaled)
    k_gemm_tf<true, 2><<<dim3(3 * H / 64, N_NODES / 128), 256>>>(p_xl, in_proj_w, in_proj_b,
                                                                 p_qkvb, N_NODES, 3 * H, H);

    // attention (bf16 tensor-core flash, cp.async pipelined K/V)
    k_attn_mma<<<dim3(N_NODES / 64, NHEAD, KSPLIT), 128>>>(p_qkvb);

    // out projection with fused split-K merge (A computed from g_pacc/g_pm/g_pl)
    k_gemm_tf<true, 0, true><<<dim3(H / 64, N_NODES / 128), 256>>>(nullptr, out_proj_w,
                                                                   out_proj_b, p_h,
                                                                   N_NODES, H, H);

    // x1 = LN(x_local + attn_out)
    k_ln<<<N_NODES, H>>>(p_xl, p_h, ln1_g, ln1_b, nullptr, p_x1);

    // FFN
    k_gemm_tf<false, 1><<<dim3(4 * H / 64, N_NODES / 128), 256>>>(p_x1, ffn_w1, ffn_b1,
                                                                  p_ffn, N_NODES, 4 * H, H);
    k_gemm_tf<false, 0><<<dim3(H / 64, N_NODES / 128), 256>>>(p_ffn, ffn_w2, ffn_b2,
                                                              p_f2, N_NODES, H, 4 * H);

    // x_final = x_local + LN(x1 + ffn_out)
    k_ln<<<N_NODES, H>>>(p_x1, p_f2, ln2_g, ln2_b, p_xl, p_xf);

    // ---- fork 2: decoder branch (s2) overlapped with classifier (main) ----
    cudaEventRecord(ev_fork2, 0);
    cudaStreamWaitEvent(s2, ev_fork2, 0);

    k_gemm_tf<false, 1><<<dim3(2 * H / 64, N_NODES / 128), 256, 0, s2>>>(p_xf, W_d1, b_d1,
                                                                         p_d1, N_NODES, 2 * H, H);
    k_d2<<<N_NODES, 32, 0, s2>>>(p_d1, W_d2, b_d2, out_reco);
    cudaEventRecord(ev_join2, s2);

    k_cls<<<N_NODES, 32>>>(p_xf, W_cls, b_cls, out_cls);
    cudaStreamWaitEvent(0, ev_join2, 0);
}